// round 1
// baseline (speedup 1.0000x reference)
#include <cuda_runtime.h>
#include <cuda_bf16.h>
#include <math.h>

#define B_ 32
#define T_ 2048
#define E_ 1024
#define A_ 1024
#define D_ 1024

#define TM 64
#define TN 64
#define TK 16

typedef unsigned long long ull;

// Scratch (no allocations allowed): device globals.
__device__ float g_dec_proj[B_ * A_];   // W_dec @ dec + b_enc, per (b, a)
__device__ float g_energy[B_ * T_];     // raw (unmasked) energies

// ---------------- packed f32x2 helpers (FFMA2 path, PTX-only) ----------------
__device__ __forceinline__ ull pk2(float x, float y) {
    ull r; asm("mov.b64 %0, {%1, %2};" : "=l"(r) : "f"(x), "f"(y)); return r;
}
__device__ __forceinline__ float2 upk2(ull a) {
    float2 f; asm("mov.b64 {%0, %1}, %2;" : "=f"(f.x), "=f"(f.y) : "l"(a)); return f;
}
__device__ __forceinline__ void ffma2(ull& d, ull a, ull b) {
    asm("fma.rn.f32x2 %0, %1, %2, %3;" : "=l"(d) : "l"(a), "l"(b), "l"(d));
}

// ---------------- kernel 1: dec_proj[b,a] = dec[b,:] . W_dec[:,a] + b_enc[a] ----
__global__ __launch_bounds__(256) void dec_proj_kernel(
    const float* __restrict__ dec_out, const float* __restrict__ W_dec,
    const float* __restrict__ b_enc)
{
    int b = blockIdx.y;
    int a = blockIdx.x * 256 + threadIdx.x;
    __shared__ float ds[D_];
    for (int i = threadIdx.x; i < D_; i += 256) ds[i] = dec_out[b * D_ + i];
    __syncthreads();
    float s = b_enc[a];
    #pragma unroll 8
    for (int d = 0; d < D_; ++d) s += ds[d] * W_dec[(size_t)d * A_ + a];
    g_dec_proj[b * A_ + a] = s;
}

// ---------------- kernel 2: fused  energy[b,t] = v . tanh(enc@W_enc + dec_proj) ----
// Block: 256 threads, computes TM=64 rows (t) for one b. Loops A in TN=64 chunks,
// K-tiled over E with both tiles staged in SMEM. Inner product uses packed
// fma.rn.f32x2: enc values duplicated into both halves at fill time, W pre-packed
// as (n, n+1) pairs, so each k-step is 1 LDS.128 + 4 LDS.64 + 8 FFMA2 per thread.
__global__ __launch_bounds__(256) void energy_kernel(
    const float* __restrict__ enc, const float* __restrict__ W,
    const float* __restrict__ v)
{
    int b  = blockIdx.y;
    int t0 = blockIdx.x * TM;
    const float* encB = enc + ((size_t)b * T_ + t0) * E_;

    __shared__ __align__(16) ull  As2[TK][TM + 1];   // enc, each float duplicated (pad kills STS conflicts)
    __shared__ __align__(16) ull  Bsp[TK][TN / 2];   // W pairs (n, n+1)
    __shared__ float red[TM][17];

    int tid = threadIdx.x;
    int mg  = tid >> 4;           // As fill: row group 0..15
    int kg  = tid & 15;           // As fill: k 0..15
    int nb  = tid & 31;           // Bs fill: pair index 0..31
    int kb  = tid >> 5;           // Bs fill: k 0..7
    int tm  = (tid >> 4) * 4;     // this thread's 4 rows
    int tn2 = (tid & 15) * 2;     // this thread's 2 column-pairs (4 cols)

    float rowsum[4] = {0.f, 0.f, 0.f, 0.f};

    for (int chunk = 0; chunk < A_ / TN; ++chunk) {
        int a0 = chunk * TN;
        ull acc01[4] = {0ull, 0ull, 0ull, 0ull};
        ull acc23[4] = {0ull, 0ull, 0ull, 0ull};

        for (int k0 = 0; k0 < E_; k0 += TK) {
            #pragma unroll
            for (int r = 0; r < 4; ++r) {
                int m = mg + r * 16;
                float x = encB[(size_t)m * E_ + k0 + kg];
                As2[kg][m] = pk2(x, x);
            }
            #pragma unroll
            for (int r = 0; r < 2; ++r) {
                int k = kb + r * 8;
                float2 w = *(const float2*)&W[(size_t)(k0 + k) * A_ + a0 + 2 * nb];
                Bsp[k][nb] = pk2(w.x, w.y);
            }
            __syncthreads();
            #pragma unroll
            for (int k = 0; k < TK; ++k) {
                ulonglong2 bb = *(const ulonglong2*)&Bsp[k][tn2];
                #pragma unroll
                for (int i = 0; i < 4; ++i) {
                    ull aa = As2[k][tm + i];
                    ffma2(acc01[i], aa, bb.x);
                    ffma2(acc23[i], aa, bb.y);
                }
            }
            __syncthreads();
        }

        // epilogue for this A-chunk: tanh(acc + dec_proj) * v, fold into row sums
        int acol = a0 + (tid & 15) * 4;
        float dp0 = g_dec_proj[b * A_ + acol + 0];
        float dp1 = g_dec_proj[b * A_ + acol + 1];
        float dp2 = g_dec_proj[b * A_ + acol + 2];
        float dp3 = g_dec_proj[b * A_ + acol + 3];
        float v0 = v[acol + 0], v1 = v[acol + 1], v2 = v[acol + 2], v3 = v[acol + 3];
        #pragma unroll
        for (int i = 0; i < 4; ++i) {
            float2 c01 = upk2(acc01[i]);
            float2 c23 = upk2(acc23[i]);
            rowsum[i] += tanhf(c01.x + dp0) * v0 + tanhf(c01.y + dp1) * v1
                       + tanhf(c23.x + dp2) * v2 + tanhf(c23.y + dp3) * v3;
        }
    }

    // reduce the 16 column-group partials per row
    #pragma unroll
    for (int i = 0; i < 4; ++i) red[tm + i][tid & 15] = rowsum[i];
    __syncthreads();
    if (tid < TM) {
        float s = 0.f;
        #pragma unroll
        for (int q = 0; q < 16; ++q) s += red[tid][q];
        g_energy[b * T_ + t0 + tid] = s;
    }
}

// ---------------- kernel 3: masked (0/1 mask, NOT -inf) softmax over T ----------
__global__ __launch_bounds__(256) void softmax_kernel(
    const int* __restrict__ x_lens, float* __restrict__ att)
{
    int b = blockIdx.x, tid = threadIdx.x;
    __shared__ float sm[T_];
    __shared__ float red[256];
    int len = x_lens[b];

    float mx = -3.4e38f;
    for (int t = tid; t < T_; t += 256) {
        float e = g_energy[b * T_ + t];
        e = (t < len) ? e : 0.0f;      // reference multiplies by 0/1 mask
        sm[t] = e;
        mx = fmaxf(mx, e);
    }
    red[tid] = mx; __syncthreads();
    for (int s = 128; s > 0; s >>= 1) {
        if (tid < s) red[tid] = fmaxf(red[tid], red[tid + s]);
        __syncthreads();
    }
    mx = red[0];
    __syncthreads();

    float lsum = 0.f;
    for (int t = tid; t < T_; t += 256) {
        float e = expf(sm[t] - mx);
        sm[t] = e;
        lsum += e;
    }
    red[tid] = lsum; __syncthreads();
    for (int s = 128; s > 0; s >>= 1) {
        if (tid < s) red[tid] += red[tid + s];
        __syncthreads();
    }
    float inv = 1.0f / red[0];
    for (int t = tid; t < T_; t += 256) att[b * T_ + t] = sm[t] * inv;
}

// ---------------- kernel 4: context[b,e] = sum_t enc[b,t,e] * att[b,t] ----------
__global__ __launch_bounds__(256) void context_kernel(
    const float* __restrict__ enc, const float* __restrict__ att,
    float* __restrict__ ctx)
{
    int b = blockIdx.y;
    int e = blockIdx.x * 256 + threadIdx.x;
    __shared__ float as_[T_];
    for (int t = threadIdx.x; t < T_; t += 256) as_[t] = att[b * T_ + t];
    __syncthreads();
    const float* ep = enc + (size_t)b * T_ * E_ + e;
    float s = 0.f;
    #pragma unroll 16
    for (int t = 0; t < T_; ++t) s += ep[(size_t)t * E_] * as_[t];
    ctx[b * E_ + e] = s;
}

// ---------------- launch -------------------------------------------------------
extern "C" void kernel_launch(void* const* d_in, const int* in_sizes, int n_in,
                              void* d_out, int out_size)
{
    const float* enc     = (const float*)d_in[0];  // [B,T,E]
    const int*   x_lens  = (const int*)  d_in[1];  // [B]
    const float* dec_out = (const float*)d_in[2];  // [B,1,D]
    // d_in[3] = att_weights_step — unused by the reference
    const float* W_enc   = (const float*)d_in[4];  // [E,A]
    const float* b_enc   = (const float*)d_in[5];  // [A]
    const float* W_dec   = (const float*)d_in[6];  // [D,A]
    const float* v       = (const float*)d_in[7];  // [A]

    float* ctx = (float*)d_out;            // [B,1,E] = 32768 floats
    float* att = (float*)d_out + B_ * E_;  // [B,T]   = 65536 floats

    dec_proj_kernel<<<dim3(A_ / 256, B_), 256>>>(dec_out, W_dec, b_enc);
    energy_kernel <<<dim3(T_ / TM, B_), 256>>>(enc, W_enc, v);
    softmax_kernel<<<B_, 256>>>(x_lens, att);
    context_kernel<<<dim3(E_ / 256, B_), 256>>>(enc, att, ctx);
}